// round 12
// baseline (speedup 1.0000x reference)
#include <cuda_runtime.h>
#include <cuda_fp16.h>
#include <cstdint>

#define N_NODES 100000
#define N_EDGES 1600000
#define IN_CH   128
#define HID     64
#define NG      256
#define OUTC    10

#define SCAN_B  1024
#define SCAN_NB ((N_NODES + SCAN_B - 1) / SCAN_B)   // 98

#define GEMM_SMEM (2 * 128 * 36 * 4 + 128 * 72 * 4)  // 73728 B
#define AGG_NBLK  ((N_NODES / 2 * 32) / 256)          // 6250

typedef unsigned long long u64;

// ---------------- scratch (device globals; no allocation) ----------------
__device__ int    g_is64;
__device__ int    g_done;
__device__ __align__(16) int    g_deg[N_NODES];
__device__ __align__(16) int    g_rowstart[N_NODES];
__device__ __align__(16) int    g_cursor[N_NODES];
__device__ __align__(16) int    g_esrc[N_EDGES];     // CSR: src per edge, bucketed by dst
__device__ __align__(16) int    g_bsum[SCAN_NB];
__device__ volatile int         g_sflag[SCAN_NB];
__device__ __align__(16) float  g_dinv[N_NODES];
__device__ __align__(16) __half g_hs [(size_t)N_NODES * HID];  // (x@W)*dinv, fp16
__device__ __align__(16) float  g_pool[NG * HID];
__device__ __align__(16) float  g_cnt [NG];

// index loader handling int64-vs-int32 edge/batch buffers
__device__ __forceinline__ int load_idx(const void* p, long long i, int is64) {
    if (is64) return (int)((const long long*)p)[i];
    return ((const int*)p)[i];
}

__device__ __forceinline__ unsigned h2_bits(__half2 h) {
    return *reinterpret_cast<unsigned*>(&h);
}
__device__ __forceinline__ float2 h2f2(unsigned b) {
    __half2 h = *reinterpret_cast<__half2*>(&b);
    return __half22float2(h);
}
__device__ __forceinline__ unsigned f2tf(float f) {
    unsigned r; asm("cvt.rna.tf32.f32 %0, %1;" : "=r"(r) : "f"(f)); return r;
}
__device__ __forceinline__ void cp16(unsigned dst, const void* src) {
    asm volatile("cp.async.cg.shared.global [%0], [%1], 16;" :: "r"(dst), "l"(src));
}

// ---------------- setup: zero counters/flags + parallel dtype sniff ----------
__global__ void k_setup(const unsigned* __restrict__ e) {
    int i = blockIdx.x * blockDim.x + threadIdx.x;
    if (i < N_NODES) g_deg[i] = 0;
    if (i < NG * HID) g_pool[i] = 0.f;
    if (i < NG) g_cnt[i] = 0.f;
    if (i < SCAN_NB) g_sflag[i] = 0;
    if (i == 0) g_done = 0;
    if (blockIdx.x == 0 && threadIdx.x < 32) {
        unsigned nz = e[2 * threadIdx.x + 1] | e[2 * (threadIdx.x + 32) + 1];
        unsigned any = __ballot_sync(0xffffffffu, nz != 0u);
        if (threadIdx.x == 0) g_is64 = (any == 0u);
    }
}

// ---------------- in-degree count over dst (2 edges/thread, wide loads) -------
__global__ void k_degcount(const void* __restrict__ ei) {
    int i = blockIdx.x * blockDim.x + threadIdx.x;
    if (i * 2 < N_EDGES) {
        int d0, d1;
        if (g_is64) {
            longlong2 v = ((const longlong2*)((const long long*)ei + N_EDGES))[i];
            d0 = (int)v.x; d1 = (int)v.y;
        } else {
            int2 v = ((const int2*)((const int*)ei + N_EDGES))[i];
            d0 = v.x; d1 = v.y;
        }
        atomicAdd(&g_deg[d0], 1);
        atomicAdd(&g_deg[d1], 1);
    }
}

// ---------------- fused scan: block scan + decoupled lookback + emit ---------
__global__ __launch_bounds__(SCAN_B) void k_scanfused() {
    __shared__ int ws[32];
    __shared__ int s_off;
    const int b = blockIdx.x;
    const int t = threadIdx.x;
    const int lane = t & 31, wid = t >> 5;
    const int i = b * SCAN_B + t;
    int d = (i < N_NODES) ? g_deg[i] : 0;
    int v = d;
#pragma unroll
    for (int o = 1; o < 32; o <<= 1) {
        int u = __shfl_up_sync(0xffffffffu, v, o);
        if (lane >= o) v += u;
    }
    if (lane == 31) ws[wid] = v;
    __syncthreads();
    if (t < 32) {
        int w = ws[t];
#pragma unroll
        for (int o = 1; o < 32; o <<= 1) {
            int u = __shfl_up_sync(0xffffffffu, w, o);
            if (t >= o) w += u;
        }
        ws[t] = w;
    }
    __syncthreads();
    if (t == 0) {
        g_bsum[b] = ws[31];
        __threadfence();
        g_sflag[b] = 1;
    }
    if (t < 32) {
        int off = 0;
        for (int base = 0; base < b; base += 32) {
            int idx = base + lane;
            bool need = (idx < b);
            while (__ballot_sync(0xffffffffu, need && (g_sflag[idx] == 0))) { }
            if (need) off += *(volatile int*)&g_bsum[idx];
        }
#pragma unroll
        for (int o = 16; o > 0; o >>= 1) off += __shfl_down_sync(0xffffffffu, off, o);
        if (lane == 0) s_off = off;
    }
    __syncthreads();
    int ex = (v - d) + (wid ? ws[wid - 1] : 0) + s_off;
    if (i < N_NODES) {
        g_rowstart[i] = ex;
        g_cursor[i]   = ex;
        g_dinv[i]     = rsqrtf((float)(d + 1));    // +1 self loop
    }
}

// ---------------- GEMM: hs = (x @ W) * dinv -----------------------------------
// tf32 tensor cores, PROPERLY ROUNDED: W pre-rounded (cvt.rna) at one-time smem
// fill; X raw via cp.async pipeline, a-fragments rounded with +0x1000 bias-add
// (exact round-half-up on the tf32 mantissa boundary).
// block tile 128x64, 8 warps 4x2, warp tile 32x32; K=128 in 4 pipelined phases.
__global__ __launch_bounds__(256) void k_gemm(const float* __restrict__ x,
                                              const float* __restrict__ W) {
    extern __shared__ __align__(16) float smem[];
    float* Xs  = smem;                    // 2 buffers of 128*36
    float* Wsm = smem + 2 * 128 * 36;     // 128*72

    const int t      = threadIdx.x;
    const int wid    = t >> 5;
    const int lane   = t & 31;
    const int warp_m = wid & 3;
    const int warp_n = wid >> 2;
    const int g      = lane >> 2;
    const int tig    = lane & 3;
    const int row0   = blockIdx.x * 128;

    const unsigned sX0 = (unsigned)__cvta_generic_to_shared(Xs);
    const unsigned sX1 = (unsigned)__cvta_generic_to_shared(Xs + 128 * 36);

    // X phase 0 via cp.async (issued first, overlaps the synchronous W fill)
#pragma unroll
    for (int i = t; i < 1024; i += 256) {
        int rr = i >> 3, k4 = i & 7;
        int gr = row0 + rr;
        if (gr >= N_NODES) gr = N_NODES - 1;
        cp16(sX0 + (unsigned)(rr * 36 + k4 * 4) * 4u, x + (size_t)gr * IN_CH + k4 * 4);
    }
    asm volatile("cp.async.commit_group;");

    // W fill: ld.global -> cvt.rna tf32 -> st.shared (one-time, 8 float4/thread)
#pragma unroll
    for (int i = t; i < 2048; i += 256) {
        int kk = i >> 4, n4 = i & 15;
        float4 v = ((const float4*)(W + (size_t)kk * HID))[n4];
        uint4 u = make_uint4(f2tf(v.x), f2tf(v.y), f2tf(v.z), f2tf(v.w));
        *(uint4*)(Wsm + kk * 72 + n4 * 4) = u;
    }

    float c[2][4][4];
#pragma unroll
    for (int mt = 0; mt < 2; mt++)
#pragma unroll
        for (int nt = 0; nt < 4; nt++)
#pragma unroll
            for (int j = 0; j < 4; j++) c[mt][nt][j] = 0.f;

    const unsigned bufs[2] = { sX0, sX1 };

    for (int ph = 0; ph < 4; ph++) {
        if (ph < 3) {
            const unsigned dst = bufs[(ph + 1) & 1];
#pragma unroll
            for (int i = t; i < 1024; i += 256) {
                int rr = i >> 3, k4 = i & 7;
                int gr = row0 + rr;
                if (gr >= N_NODES) gr = N_NODES - 1;
                cp16(dst + (unsigned)(rr * 36 + k4 * 4) * 4u,
                     x + (size_t)gr * IN_CH + (ph + 1) * 32 + k4 * 4);
            }
            asm volatile("cp.async.commit_group;");
            asm volatile("cp.async.wait_group 1;");
        } else {
            asm volatile("cp.async.wait_group 0;");
        }
        __syncthreads();

        const unsigned* Xu = (const unsigned*)(Xs + (ph & 1) * 128 * 36);
        const unsigned* Wu = (const unsigned*)Wsm;

#pragma unroll
        for (int ks = 0; ks < 4; ks++) {
            const int k_off = ks * 8;
            unsigned a[2][4], bfr[4][2];
#pragma unroll
            for (int mt = 0; mt < 2; mt++) {
                int br = warp_m * 32 + mt * 16 + g;
                a[mt][0] = Xu[br * 36 + k_off + tig] + 0x1000u;
                a[mt][1] = Xu[(br + 8) * 36 + k_off + tig] + 0x1000u;
                a[mt][2] = Xu[br * 36 + k_off + tig + 4] + 0x1000u;
                a[mt][3] = Xu[(br + 8) * 36 + k_off + tig + 4] + 0x1000u;
            }
            const int krow = ph * 32 + k_off + tig;
#pragma unroll
            for (int nt = 0; nt < 4; nt++) {
                int n_off = warp_n * 32 + nt * 8 + g;
                bfr[nt][0] = Wu[krow * 72 + n_off];
                bfr[nt][1] = Wu[(krow + 4) * 72 + n_off];
            }
#pragma unroll
            for (int mt = 0; mt < 2; mt++)
#pragma unroll
                for (int nt = 0; nt < 4; nt++) {
                    asm("mma.sync.aligned.m16n8k8.row.col.f32.tf32.tf32.f32 "
                        "{%0,%1,%2,%3}, {%4,%5,%6,%7}, {%8,%9}, {%0,%1,%2,%3};"
                        : "+f"(c[mt][nt][0]), "+f"(c[mt][nt][1]),
                          "+f"(c[mt][nt][2]), "+f"(c[mt][nt][3])
                        : "r"(a[mt][0]), "r"(a[mt][1]), "r"(a[mt][2]), "r"(a[mt][3]),
                          "r"(bfr[nt][0]), "r"(bfr[nt][1]));
                }
        }
        __syncthreads();
    }

    // epilogue: scale by dinv, pack fp16, store
#pragma unroll
    for (int mt = 0; mt < 2; mt++) {
        int r0 = row0 + warp_m * 32 + mt * 16 + g;
        int r1 = r0 + 8;
        float dv0 = (r0 < N_NODES) ? g_dinv[r0] : 0.f;
        float dv1 = (r1 < N_NODES) ? g_dinv[r1] : 0.f;
#pragma unroll
        for (int nt = 0; nt < 4; nt++) {
            int col = warp_n * 32 + nt * 8 + tig * 2;
            if (r0 < N_NODES) {
                __half2 h = __floats2half2_rn(c[mt][nt][0] * dv0, c[mt][nt][1] * dv0);
                *(unsigned*)(g_hs + (size_t)r0 * HID + col) = h2_bits(h);
            }
            if (r1 < N_NODES) {
                __half2 h = __floats2half2_rn(c[mt][nt][2] * dv1, c[mt][nt][3] * dv1);
                *(unsigned*)(g_hs + (size_t)r1 * HID + col) = h2_bits(h);
            }
        }
    }
}

// ---------------- CSR fill: bucket src by dst (2 edges/thread) ----------------
__global__ void k_fill(const void* __restrict__ ei) {
    int i = blockIdx.x * blockDim.x + threadIdx.x;
    if (i * 2 < N_EDGES) {
        int s0, s1, d0, d1;
        if (g_is64) {
            longlong2 sv = ((const longlong2*)ei)[i];
            longlong2 dv = ((const longlong2*)((const long long*)ei + N_EDGES))[i];
            s0 = (int)sv.x; s1 = (int)sv.y; d0 = (int)dv.x; d1 = (int)dv.y;
        } else {
            int2 sv = ((const int2*)ei)[i];
            int2 dv = ((const int2*)((const int*)ei + N_EDGES))[i];
            s0 = sv.x; s1 = sv.y; d0 = dv.x; d1 = dv.y;
        }
        g_esrc[atomicAdd(&g_cursor[d0], 1)] = s0;
        g_esrc[atomicAdd(&g_cursor[d1], 1)] = s1;
    }
}

// ---------------- aggregate + relu + smem pool + last-block final -------------
__global__ __launch_bounds__(256) void k_agg(const void* __restrict__ batch,
                                             const float* __restrict__ bconv,
                                             const float* __restrict__ Wl,
                                             const float* __restrict__ bl,
                                             float* __restrict__ out) {
    __shared__ __align__(16) float sp[16 * 64];   // slot-major pool accum
    __shared__ int scnt[16];
    __shared__ int sglo;
    __shared__ int s_last;

    const int t    = threadIdx.x;
    const int gt   = blockIdx.x * 256 + t;
    const int warp = gt >> 5;
    const int lane = gt & 31;
    const int node = warp * 2 + (lane >> 4);
    const int hl   = lane & 15;
    const int is64 = g_is64;
    const uint2* hp = (const uint2*)g_hs;    // row = 16 uint2 (128B)

    if (t == 0) sglo = load_idx(batch, blockIdx.x * 16, is64);
    if (t < 16) scnt[t] = 0;
#pragma unroll
    for (int i = t; i < 1024; i += 256) sp[i] = 0.f;
    __syncthreads();

    // self-loop term
    uint2 u = hp[(size_t)node * 16 + hl];
    float2 sa = h2f2(u.x);
    float2 sb = h2f2(u.y);

    const int rs = g_rowstart[node];
    const int d  = g_deg[node];
    const int* ep = g_esrc + rs;

    int e = 0;
    for (; e + 8 <= d; e += 8) {
        int s[8];
#pragma unroll
        for (int j = 0; j < 8; j++) s[j] = __ldg(ep + e + j);
        float2 pa0 = make_float2(0.f, 0.f), pa1 = pa0, pa2 = pa0, pa3 = pa0;
        float2 pb0 = pa0, pb1 = pa0, pb2 = pa0, pb3 = pa0;
#pragma unroll
        for (int j = 0; j < 8; j += 4) {
            uint2 v0 = hp[(size_t)s[j + 0] * 16 + hl];
            uint2 v1 = hp[(size_t)s[j + 1] * 16 + hl];
            uint2 v2 = hp[(size_t)s[j + 2] * 16 + hl];
            uint2 v3 = hp[(size_t)s[j + 3] * 16 + hl];
            float2 a0 = h2f2(v0.x), b0 = h2f2(v0.y);
            float2 a1 = h2f2(v1.x), b1 = h2f2(v1.y);
            float2 a2 = h2f2(v2.x), b2 = h2f2(v2.y);
            float2 a3 = h2f2(v3.x), b3 = h2f2(v3.y);
            pa0.x += a0.x; pa0.y += a0.y; pb0.x += b0.x; pb0.y += b0.y;
            pa1.x += a1.x; pa1.y += a1.y; pb1.x += b1.x; pb1.y += b1.y;
            pa2.x += a2.x; pa2.y += a2.y; pb2.x += b2.x; pb2.y += b2.y;
            pa3.x += a3.x; pa3.y += a3.y; pb3.x += b3.x; pb3.y += b3.y;
        }
        sa.x += (pa0.x + pa1.x) + (pa2.x + pa3.x);
        sa.y += (pa0.y + pa1.y) + (pa2.y + pa3.y);
        sb.x += (pb0.x + pb1.x) + (pb2.x + pb3.x);
        sb.y += (pb0.y + pb1.y) + (pb2.y + pb3.y);
    }
    for (; e < d; e++) {
        uint2 v = hp[(size_t)__ldg(ep + e) * 16 + hl];
        float2 a = h2f2(v.x), b = h2f2(v.y);
        sa.x += a.x; sa.y += a.y; sb.x += b.x; sb.y += b.y;
    }

    const float dv = g_dinv[node];
    float4 bb = ((const float4*)bconv)[hl];
    float h0 = fmaxf(fmaf(dv, sa.x, bb.x), 0.f);
    float h1 = fmaxf(fmaf(dv, sa.y, bb.y), 0.f);
    float h2 = fmaxf(fmaf(dv, sb.x, bb.z), 0.f);
    float h3 = fmaxf(fmaf(dv, sb.y, bb.w), 0.f);

    const int g = load_idx(batch, node, is64);
    const int slot = g - sglo;
    if (slot < 16) {
        float* q = sp + slot * 64 + hl * 4;
        atomicAdd(q + 0, h0);
        atomicAdd(q + 1, h1);
        atomicAdd(q + 2, h2);
        atomicAdd(q + 3, h3);
        if (hl == 0) atomicAdd(&scnt[slot], 1);
    } else {
        float* pp = g_pool + g * HID + hl * 4;
        asm volatile("red.global.add.v4.f32 [%0], {%1, %2, %3, %4};"
                     :: "l"(pp), "f"(h0), "f"(h1), "f"(h2), "f"(h3) : "memory");
        if (hl == 0) atomicAdd(&g_cnt[g], 1.0f);
    }
    __syncthreads();

    // flush used slots: thread t -> slot t>>4, quad t&15
    const int fs = t >> 4, fq = t & 15;
    const int n = scnt[fs];
    if (n > 0) {
        const int gg = sglo + fs;
        float4 v = *(const float4*)(sp + fs * 64 + fq * 4);
        float* pp = g_pool + gg * HID + fq * 4;
        asm volatile("red.global.add.v4.f32 [%0], {%1, %2, %3, %4};"
                     :: "l"(pp), "f"(v.x), "f"(v.y), "f"(v.z), "f"(v.w) : "memory");
        if (fq == 0) atomicAdd(&g_cnt[gg], (float)n);
    }

    // ---- last block computes the final linear (replaces k_final launch) ----
    if (t == 0) {
        __threadfence();
        s_last = (atomicAdd(&g_done, 1) == AGG_NBLK - 1);
    }
    __syncthreads();
    if (s_last) {
        __threadfence();
        // reuse sp: sW at [0,640), sb at [640,650)
        for (int i = t; i < HID * OUTC; i += 256) sp[i] = Wl[i];
        if (t < OUTC) sp[640 + t] = bl[t];
        __syncthreads();
        const float inv = 1.f / fmaxf(g_cnt[t], 1.f);
        float acc[OUTC];
#pragma unroll
        for (int j = 0; j < OUTC; j++) acc[j] = sp[640 + j];
#pragma unroll 4
        for (int c = 0; c < HID; c++) {
            float p = g_pool[t * HID + c] * inv;
#pragma unroll
            for (int j = 0; j < OUTC; j++) acc[j] = fmaf(p, sp[c * OUTC + j], acc[j]);
        }
#pragma unroll
        for (int j = 0; j < OUTC; j++) out[t * OUTC + j] = acc[j];
    }
}

// ---------------- launch ----------------
extern "C" void kernel_launch(void* const* d_in, const int* in_sizes, int n_in,
                              void* d_out, int out_size) {
    const float* x     = (const float*)d_in[0];
    const void*  ei    = d_in[1];
    const void*  batch = d_in[2];
    const float* Wc    = (const float*)d_in[3];
    const float* bc    = (const float*)d_in[4];
    const float* Wl    = (const float*)d_in[5];
    const float* bl    = (const float*)d_in[6];
    float*       out   = (float*)d_out;

    cudaFuncSetAttribute(k_gemm, cudaFuncAttributeMaxDynamicSharedMemorySize, GEMM_SMEM);

    k_setup     <<<(N_NODES + 255) / 256, 256>>>((const unsigned*)ei);
    k_degcount  <<<(N_EDGES / 2 + 255) / 256, 256>>>(ei);
    k_scanfused <<<SCAN_NB, SCAN_B>>>();
    k_gemm      <<<(N_NODES + 127) / 128, 256, GEMM_SMEM>>>(x, Wc);   // index 3: profiled
    k_fill      <<<(N_EDGES / 2 + 255) / 256, 256>>>(ei);
    k_agg       <<<AGG_NBLK, 256>>>(batch, bc, Wl, bl, out);
}

// round 13
// speedup vs baseline: 1.0685x; 1.0685x over previous
#include <cuda_runtime.h>
#include <cuda_fp16.h>
#include <cstdint>

#define N_NODES 100000
#define N_EDGES 1600000
#define IN_CH   128
#define HID     64
#define NG      256
#define OUTC    10

#define SCAN_B  1024
#define SCAN_NB ((N_NODES + SCAN_B - 1) / SCAN_B)   // 98

#define GEMM_SMEM (2 * 128 * 36 * 4 + 128 * 72 * 4)  // 73728 B

typedef unsigned long long u64;

// ---------------- scratch (device globals; no allocation) ----------------
__device__ int    g_is64;
__device__ __align__(16) int    g_deg[N_NODES];
__device__ __align__(16) int    g_rowstart[N_NODES];
__device__ __align__(16) int    g_cursor[N_NODES];
__device__ __align__(16) int    g_esrc[N_EDGES];     // CSR: src per edge, bucketed by dst
__device__ __align__(16) int    g_bsum[SCAN_NB];
__device__ volatile int         g_sflag[SCAN_NB];
__device__ __align__(16) float  g_dinv[N_NODES];
__device__ __align__(16) __half g_hs [(size_t)N_NODES * HID];  // (x@W)*dinv, fp16
__device__ __align__(16) float  g_pool[NG * HID];
__device__ __align__(16) float  g_cnt [NG];

// index loader handling int64-vs-int32 edge/batch buffers
__device__ __forceinline__ int load_idx(const void* p, long long i, int is64) {
    if (is64) return (int)((const long long*)p)[i];
    return ((const int*)p)[i];
}

__device__ __forceinline__ unsigned h2_bits(__half2 h) {
    return *reinterpret_cast<unsigned*>(&h);
}
__device__ __forceinline__ float2 h2f2(unsigned b) {
    __half2 h = *reinterpret_cast<__half2*>(&b);
    return __half22float2(h);
}
__device__ __forceinline__ unsigned f2tf(float f) {
    unsigned r; asm("cvt.rna.tf32.f32 %0, %1;" : "=r"(r) : "f"(f)); return r;
}
__device__ __forceinline__ void cp16(unsigned dst, const void* src) {
    asm volatile("cp.async.cg.shared.global [%0], [%1], 16;" :: "r"(dst), "l"(src));
}

// ---------------- setup: zero counters/flags + parallel dtype sniff ----------
__global__ void k_setup(const unsigned* __restrict__ e) {
    int i = blockIdx.x * blockDim.x + threadIdx.x;
    if (i < N_NODES) g_deg[i] = 0;
    if (i < NG * HID) g_pool[i] = 0.f;
    if (i < NG) g_cnt[i] = 0.f;
    if (i < SCAN_NB) g_sflag[i] = 0;
    if (blockIdx.x == 0 && threadIdx.x < 32) {
        unsigned nz = e[2 * threadIdx.x + 1] | e[2 * (threadIdx.x + 32) + 1];
        unsigned any = __ballot_sync(0xffffffffu, nz != 0u);
        if (threadIdx.x == 0) g_is64 = (any == 0u);
    }
}

// ---------------- in-degree count over dst (2 edges/thread, wide loads) -------
__global__ void k_degcount(const void* __restrict__ ei) {
    int i = blockIdx.x * blockDim.x + threadIdx.x;
    if (i * 2 < N_EDGES) {
        int d0, d1;
        if (g_is64) {
            longlong2 v = ((const longlong2*)((const long long*)ei + N_EDGES))[i];
            d0 = (int)v.x; d1 = (int)v.y;
        } else {
            int2 v = ((const int2*)((const int*)ei + N_EDGES))[i];
            d0 = v.x; d1 = v.y;
        }
        atomicAdd(&g_deg[d0], 1);
        atomicAdd(&g_deg[d1], 1);
    }
}

// ---------------- fused scan: block scan + decoupled lookback + emit ---------
__global__ __launch_bounds__(SCAN_B) void k_scanfused() {
    __shared__ int ws[32];
    __shared__ int s_off;
    const int b = blockIdx.x;
    const int t = threadIdx.x;
    const int lane = t & 31, wid = t >> 5;
    const int i = b * SCAN_B + t;
    int d = (i < N_NODES) ? g_deg[i] : 0;
    int v = d;
#pragma unroll
    for (int o = 1; o < 32; o <<= 1) {
        int u = __shfl_up_sync(0xffffffffu, v, o);
        if (lane >= o) v += u;
    }
    if (lane == 31) ws[wid] = v;
    __syncthreads();
    if (t < 32) {
        int w = ws[t];
#pragma unroll
        for (int o = 1; o < 32; o <<= 1) {
            int u = __shfl_up_sync(0xffffffffu, w, o);
            if (t >= o) w += u;
        }
        ws[t] = w;
    }
    __syncthreads();
    if (t == 0) {
        g_bsum[b] = ws[31];
        __threadfence();
        g_sflag[b] = 1;
    }
    if (t < 32) {
        int off = 0;
        for (int base = 0; base < b; base += 32) {
            int idx = base + lane;
            bool need = (idx < b);
            while (__ballot_sync(0xffffffffu, need && (g_sflag[idx] == 0))) { }
            if (need) off += *(volatile int*)&g_bsum[idx];
        }
#pragma unroll
        for (int o = 16; o > 0; o >>= 1) off += __shfl_down_sync(0xffffffffu, off, o);
        if (lane == 0) s_off = off;
    }
    __syncthreads();
    int ex = (v - d) + (wid ? ws[wid - 1] : 0) + s_off;
    if (i < N_NODES) {
        g_rowstart[i] = ex;
        g_cursor[i]   = ex;
        g_dinv[i]     = rsqrtf((float)(d + 1));    // +1 self loop
    }
}

// ---------------- GEMM: hs = (x @ W) * dinv -----------------------------------
// tf32 tensor cores, properly rounded: W pre-rounded (cvt.rna) at one-time smem
// fill; X raw via cp.async pipeline, a-fragments rounded with +0x1000 bias-add.
// block tile 128x64, 8 warps 4x2, warp tile 32x32; K=128 in 4 pipelined phases.
__global__ __launch_bounds__(256) void k_gemm(const float* __restrict__ x,
                                              const float* __restrict__ W) {
    extern __shared__ __align__(16) float smem[];
    float* Xs  = smem;                    // 2 buffers of 128*36
    float* Wsm = smem + 2 * 128 * 36;     // 128*72

    const int t      = threadIdx.x;
    const int wid    = t >> 5;
    const int lane   = t & 31;
    const int warp_m = wid & 3;
    const int warp_n = wid >> 2;
    const int g      = lane >> 2;
    const int tig    = lane & 3;
    const int row0   = blockIdx.x * 128;

    const unsigned sX0 = (unsigned)__cvta_generic_to_shared(Xs);
    const unsigned sX1 = (unsigned)__cvta_generic_to_shared(Xs + 128 * 36);

    // X phase 0 via cp.async (issued first, overlaps the synchronous W fill)
#pragma unroll
    for (int i = t; i < 1024; i += 256) {
        int rr = i >> 3, k4 = i & 7;
        int gr = row0 + rr;
        if (gr >= N_NODES) gr = N_NODES - 1;
        cp16(sX0 + (unsigned)(rr * 36 + k4 * 4) * 4u, x + (size_t)gr * IN_CH + k4 * 4);
    }
    asm volatile("cp.async.commit_group;");

    // W fill: ld.global -> cvt.rna tf32 -> st.shared (one-time)
#pragma unroll
    for (int i = t; i < 2048; i += 256) {
        int kk = i >> 4, n4 = i & 15;
        float4 v = ((const float4*)(W + (size_t)kk * HID))[n4];
        uint4 u = make_uint4(f2tf(v.x), f2tf(v.y), f2tf(v.z), f2tf(v.w));
        *(uint4*)(Wsm + kk * 72 + n4 * 4) = u;
    }

    float c[2][4][4];
#pragma unroll
    for (int mt = 0; mt < 2; mt++)
#pragma unroll
        for (int nt = 0; nt < 4; nt++)
#pragma unroll
            for (int j = 0; j < 4; j++) c[mt][nt][j] = 0.f;

    const unsigned bufs[2] = { sX0, sX1 };

    for (int ph = 0; ph < 4; ph++) {
        if (ph < 3) {
            const unsigned dst = bufs[(ph + 1) & 1];
#pragma unroll
            for (int i = t; i < 1024; i += 256) {
                int rr = i >> 3, k4 = i & 7;
                int gr = row0 + rr;
                if (gr >= N_NODES) gr = N_NODES - 1;
                cp16(dst + (unsigned)(rr * 36 + k4 * 4) * 4u,
                     x + (size_t)gr * IN_CH + (ph + 1) * 32 + k4 * 4);
            }
            asm volatile("cp.async.commit_group;");
            asm volatile("cp.async.wait_group 1;");
        } else {
            asm volatile("cp.async.wait_group 0;");
        }
        __syncthreads();

        const unsigned* Xu = (const unsigned*)(Xs + (ph & 1) * 128 * 36);
        const unsigned* Wu = (const unsigned*)Wsm;

#pragma unroll
        for (int ks = 0; ks < 4; ks++) {
            const int k_off = ks * 8;
            unsigned a[2][4], bfr[4][2];
#pragma unroll
            for (int mt = 0; mt < 2; mt++) {
                int br = warp_m * 32 + mt * 16 + g;
                a[mt][0] = Xu[br * 36 + k_off + tig] + 0x1000u;
                a[mt][1] = Xu[(br + 8) * 36 + k_off + tig] + 0x1000u;
                a[mt][2] = Xu[br * 36 + k_off + tig + 4] + 0x1000u;
                a[mt][3] = Xu[(br + 8) * 36 + k_off + tig + 4] + 0x1000u;
            }
            const int krow = ph * 32 + k_off + tig;
#pragma unroll
            for (int nt = 0; nt < 4; nt++) {
                int n_off = warp_n * 32 + nt * 8 + g;
                bfr[nt][0] = Wu[krow * 72 + n_off];
                bfr[nt][1] = Wu[(krow + 4) * 72 + n_off];
            }
#pragma unroll
            for (int mt = 0; mt < 2; mt++)
#pragma unroll
                for (int nt = 0; nt < 4; nt++) {
                    asm("mma.sync.aligned.m16n8k8.row.col.f32.tf32.tf32.f32 "
                        "{%0,%1,%2,%3}, {%4,%5,%6,%7}, {%8,%9}, {%0,%1,%2,%3};"
                        : "+f"(c[mt][nt][0]), "+f"(c[mt][nt][1]),
                          "+f"(c[mt][nt][2]), "+f"(c[mt][nt][3])
                        : "r"(a[mt][0]), "r"(a[mt][1]), "r"(a[mt][2]), "r"(a[mt][3]),
                          "r"(bfr[nt][0]), "r"(bfr[nt][1]));
                }
        }
        __syncthreads();
    }

    // epilogue: scale by dinv, pack fp16, store
#pragma unroll
    for (int mt = 0; mt < 2; mt++) {
        int r0 = row0 + warp_m * 32 + mt * 16 + g;
        int r1 = r0 + 8;
        float dv0 = (r0 < N_NODES) ? g_dinv[r0] : 0.f;
        float dv1 = (r1 < N_NODES) ? g_dinv[r1] : 0.f;
#pragma unroll
        for (int nt = 0; nt < 4; nt++) {
            int col = warp_n * 32 + nt * 8 + tig * 2;
            if (r0 < N_NODES) {
                __half2 h = __floats2half2_rn(c[mt][nt][0] * dv0, c[mt][nt][1] * dv0);
                *(unsigned*)(g_hs + (size_t)r0 * HID + col) = h2_bits(h);
            }
            if (r1 < N_NODES) {
                __half2 h = __floats2half2_rn(c[mt][nt][2] * dv1, c[mt][nt][3] * dv1);
                *(unsigned*)(g_hs + (size_t)r1 * HID + col) = h2_bits(h);
            }
        }
    }
}

// ---------------- CSR fill: bucket src by dst (2 edges/thread) ----------------
__global__ void k_fill(const void* __restrict__ ei) {
    int i = blockIdx.x * blockDim.x + threadIdx.x;
    if (i * 2 < N_EDGES) {
        int s0, s1, d0, d1;
        if (g_is64) {
            longlong2 sv = ((const longlong2*)ei)[i];
            longlong2 dv = ((const longlong2*)((const long long*)ei + N_EDGES))[i];
            s0 = (int)sv.x; s1 = (int)sv.y; d0 = (int)dv.x; d1 = (int)dv.y;
        } else {
            int2 sv = ((const int2*)ei)[i];
            int2 dv = ((const int2*)((const int*)ei + N_EDGES))[i];
            s0 = sv.x; s1 = sv.y; d0 = dv.x; d1 = dv.y;
        }
        g_esrc[atomicAdd(&g_cursor[d0], 1)] = s0;
        g_esrc[atomicAdd(&g_cursor[d1], 1)] = s1;
    }
}

// ---------------- aggregate + relu + smem-pooled reduction ----------------
__global__ __launch_bounds__(256) void k_agg(const void* __restrict__ batch,
                                             const float* __restrict__ bconv) {
    __shared__ __align__(16) float sp[16 * 64];   // slot-major pool accum
    __shared__ int scnt[16];
    __shared__ int sglo;

    const int t    = threadIdx.x;
    const int gt   = blockIdx.x * 256 + t;
    const int warp = gt >> 5;
    const int lane = gt & 31;
    const int node = warp * 2 + (lane >> 4);
    const int hl   = lane & 15;
    const int is64 = g_is64;
    const uint2* hp = (const uint2*)g_hs;    // row = 16 uint2 (128B)

    if (t == 0) sglo = load_idx(batch, blockIdx.x * 16, is64);
    if (t < 16) scnt[t] = 0;
#pragma unroll
    for (int i = t; i < 1024; i += 256) sp[i] = 0.f;
    __syncthreads();

    // self-loop term
    uint2 u = hp[(size_t)node * 16 + hl];
    float2 sa = h2f2(u.x);
    float2 sb = h2f2(u.y);

    const int rs = g_rowstart[node];
    const int d  = g_deg[node];
    const int* ep = g_esrc + rs;

    int e = 0;
    for (; e + 8 <= d; e += 8) {
        int s[8];
#pragma unroll
        for (int j = 0; j < 8; j++) s[j] = __ldg(ep + e + j);
        float2 pa0 = make_float2(0.f, 0.f), pa1 = pa0, pa2 = pa0, pa3 = pa0;
        float2 pb0 = pa0, pb1 = pa0, pb2 = pa0, pb3 = pa0;
#pragma unroll
        for (int j = 0; j < 8; j += 4) {
            uint2 v0 = hp[(size_t)s[j + 0] * 16 + hl];
            uint2 v1 = hp[(size_t)s[j + 1] * 16 + hl];
            uint2 v2 = hp[(size_t)s[j + 2] * 16 + hl];
            uint2 v3 = hp[(size_t)s[j + 3] * 16 + hl];
            float2 a0 = h2f2(v0.x), b0 = h2f2(v0.y);
            float2 a1 = h2f2(v1.x), b1 = h2f2(v1.y);
            float2 a2 = h2f2(v2.x), b2 = h2f2(v2.y);
            float2 a3 = h2f2(v3.x), b3 = h2f2(v3.y);
            pa0.x += a0.x; pa0.y += a0.y; pb0.x += b0.x; pb0.y += b0.y;
            pa1.x += a1.x; pa1.y += a1.y; pb1.x += b1.x; pb1.y += b1.y;
            pa2.x += a2.x; pa2.y += a2.y; pb2.x += b2.x; pb2.y += b2.y;
            pa3.x += a3.x; pa3.y += a3.y; pb3.x += b3.x; pb3.y += b3.y;
        }
        sa.x += (pa0.x + pa1.x) + (pa2.x + pa3.x);
        sa.y += (pa0.y + pa1.y) + (pa2.y + pa3.y);
        sb.x += (pb0.x + pb1.x) + (pb2.x + pb3.x);
        sb.y += (pb0.y + pb1.y) + (pb2.y + pb3.y);
    }
    for (; e < d; e++) {
        uint2 v = hp[(size_t)__ldg(ep + e) * 16 + hl];
        float2 a = h2f2(v.x), b = h2f2(v.y);
        sa.x += a.x; sa.y += a.y; sb.x += b.x; sb.y += b.y;
    }

    const float dv = g_dinv[node];
    float4 bb = ((const float4*)bconv)[hl];
    float h0 = fmaxf(fmaf(dv, sa.x, bb.x), 0.f);
    float h1 = fmaxf(fmaf(dv, sa.y, bb.y), 0.f);
    float h2 = fmaxf(fmaf(dv, sb.x, bb.z), 0.f);
    float h3 = fmaxf(fmaf(dv, sb.y, bb.w), 0.f);

    const int g = load_idx(batch, node, is64);
    const int slot = g - sglo;
    if (slot < 16) {
        float* q = sp + slot * 64 + hl * 4;
        atomicAdd(q + 0, h0);
        atomicAdd(q + 1, h1);
        atomicAdd(q + 2, h2);
        atomicAdd(q + 3, h3);
        if (hl == 0) atomicAdd(&scnt[slot], 1);
    } else {
        float* pp = g_pool + g * HID + hl * 4;
        asm volatile("red.global.add.v4.f32 [%0], {%1, %2, %3, %4};"
                     :: "l"(pp), "f"(h0), "f"(h1), "f"(h2), "f"(h3) : "memory");
        if (hl == 0) atomicAdd(&g_cnt[g], 1.0f);
    }
    __syncthreads();

    // flush used slots: thread t -> slot t>>4, quad t&15
    const int fs = t >> 4, fq = t & 15;
    const int n = scnt[fs];
    if (n > 0) {
        const int gg = sglo + fs;
        float4 v = *(const float4*)(sp + fs * 64 + fq * 4);
        float* pp = g_pool + gg * HID + fq * 4;
        asm volatile("red.global.add.v4.f32 [%0], {%1, %2, %3, %4};"
                     :: "l"(pp), "f"(v.x), "f"(v.y), "f"(v.z), "f"(v.w) : "memory");
        if (fq == 0) atomicAdd(&g_cnt[gg], (float)n);
    }
}

// ---------------- final: out = (pool/cnt) @ W_lin + b_lin ----------------
__global__ __launch_bounds__(256) void k_final(const float* __restrict__ Wl,
                                               const float* __restrict__ bl,
                                               float* __restrict__ out) {
    __shared__ float sW[HID * OUTC];
    __shared__ float sb[OUTC];
    const int t = threadIdx.x;
    for (int i = t; i < HID * OUTC; i += 256) sW[i] = Wl[i];
    if (t < OUTC) sb[t] = bl[t];
    __syncthreads();

    const float inv = 1.f / fmaxf(g_cnt[t], 1.f);
    float acc[OUTC];
#pragma unroll
    for (int j = 0; j < OUTC; j++) acc[j] = sb[j];
#pragma unroll 4
    for (int c = 0; c < HID; c++) {
        float p = g_pool[t * HID + c] * inv;
#pragma unroll
        for (int j = 0; j < OUTC; j++) acc[j] = fmaf(p, sW[c * OUTC + j], acc[j]);
    }
#pragma unroll
    for (int j = 0; j < OUTC; j++) out[t * OUTC + j] = acc[j];
}

// ---------------- launch: fork k_gemm onto a side stream, parallel to k_fill --
extern "C" void kernel_launch(void* const* d_in, const int* in_sizes, int n_in,
                              void* d_out, int out_size) {
    const float* x     = (const float*)d_in[0];
    const void*  ei    = d_in[1];
    const void*  batch = d_in[2];
    const float* Wc    = (const float*)d_in[3];
    const float* bc    = (const float*)d_in[4];
    const float* Wl    = (const float*)d_in[5];
    const float* bl    = (const float*)d_in[6];
    float*       out   = (float*)d_out;

    cudaFuncSetAttribute(k_gemm, cudaFuncAttributeMaxDynamicSharedMemorySize, GEMM_SMEM);

    // fresh per-call fork/join handles (kernel_launch runs only a handful of
    // times — correctness + capture; handles are never device memory)
    cudaStream_t s1;
    cudaEvent_t evA, evB;
    cudaStreamCreateWithFlags(&s1, cudaStreamNonBlocking);
    cudaEventCreateWithFlags(&evA, cudaEventDisableTiming);
    cudaEventCreateWithFlags(&evB, cudaEventDisableTiming);

    k_setup     <<<(N_NODES + 255) / 256, 256>>>((const unsigned*)ei);
    k_degcount  <<<(N_EDGES / 2 + 255) / 256, 256>>>(ei);
    k_scanfused <<<SCAN_NB, SCAN_B>>>();

    // fork: gemm (needs dinv) runs on s1 in parallel with fill (needs cursor)
    cudaEventRecord(evA, 0);
    cudaStreamWaitEvent(s1, evA, 0);
    k_gemm      <<<(N_NODES + 127) / 128, 256, GEMM_SMEM, s1>>>(x, Wc);
    cudaEventRecord(evB, s1);

    k_fill      <<<(N_EDGES / 2 + 255) / 256, 256>>>(ei);

    // join: agg needs both hs (gemm) and esrc (fill)
    cudaStreamWaitEvent(0, evB, 0);
    k_agg       <<<(N_NODES / 2 * 32) / 256, 256>>>(batch, bc);
    k_final     <<<1, 256>>>(Wl, bl, out);
}